// round 2
// baseline (speedup 1.0000x reference)
#include <cuda_runtime.h>
#include <cuda_fp16.h>
#include <stdint.h>

// Fixed problem shapes
#define NLAT_IN   181
#define NLON_IN   360
#define NLAT_OUT  361
#define NLON_OUT  720
#define KSIZE     3
#define CIN       16
#define COUT      16
#define NNZ_MAX   8192

#define X_CI_STRIDE (NLAT_IN * NLON_IN)          // 65160
#define RINGS       (KSIZE * NLAT_IN)            // 543
#define PLANE       (RINGS * NLON_IN)            // 195480 (uint2 elems per plane)
#define NBINS       (NLAT_OUT * 2)               // 722 (lat, parity)
#define SCAN_P      768
#define SE_MAX      512

// Scratch (device globals — no dynamic allocation allowed)
__device__ uint2 g_xwp[4][PLANE];        // xw in fp16: plane cg holds co {4cg..4cg+3}, 6.25 MB
__device__ int   g_starts[NBINS + 2];
__device__ int2  g_entries[NNZ_MAX];     // .x = base(18b) | shift<<18 ; .y = bits(val)

// ---------------------------------------------------------------------------
// K1: channel-mix einsum (fp32 accum -> fp16 store) + fused sparse binning.
// grid (NLAT_IN+1, 4), 384 threads. Block (NLAT_IN, 0) does the binning.
__global__ __launch_bounds__(384) void einsum_prep_kernel(
    const float* __restrict__ x, const float* __restrict__ weight,
    const int* __restrict__ ker_idx, const int* __restrict__ row_idx,
    const int* __restrict__ col_idx, const float* __restrict__ vals, int nnz)
{
    const int tin = blockIdx.x;
    const int cg  = blockIdx.y;
    const int t   = threadIdx.x;
    const int nt  = blockDim.x;   // 384

    if (tin == NLAT_IN) {
        if (cg != 0) return;
        // ---------------- binning: count -> scan -> fill, all in smem --------
        __shared__ int bufA[SCAN_P], bufB[SCAN_P];
        __shared__ int scnt[NBINS], scur[NBINS];

        for (int i = t; i < SCAN_P; i += nt) bufA[i] = 0;
        __syncthreads();
        for (int i = t; i < nnz; i += nt) {
            int col = col_idx[i];
            int hi  = col / NLON_OUT;
            atomicAdd(&bufA[hi * 2 + (col & 1)], 1);   // p parity == col parity
        }
        __syncthreads();
        for (int i = t; i < NBINS; i += nt) scnt[i] = bufA[i];
        __syncthreads();
        // Hillis-Steele inclusive scan over SCAN_P, ping-pong buffers
        int* src = bufA; int* dst = bufB;
        for (int off = 1; off < SCAN_P; off <<= 1) {
            for (int i = t; i < SCAN_P; i += nt) {
                int v = src[i];
                if (i >= off) v += src[i - off];
                dst[i] = v;
            }
            __syncthreads();
            int* tmp = src; src = dst; dst = tmp;
        }
        for (int i = t; i < NBINS; i += nt) {
            g_starts[i + 1] = src[i];
            scur[i] = src[i] - scnt[i];    // exclusive prefix = bin start
        }
        if (t == 0) g_starts[0] = 0;
        __syncthreads();
        for (int i = t; i < nnz; i += nt) {
            int col = col_idx[i];
            int hi  = col / NLON_OUT;
            int p   = col - hi * NLON_OUT;
            int key = hi * 2 + (p & 1);
            int pos = atomicAdd(&scur[key], 1);
            int base = (ker_idx[i] * NLAT_IN + row_idx[i]) * NLON_IN;  // < 2^18
            g_entries[pos] = make_int2(base | ((p >> 1) << 18), __float_as_int(vals[i]));
        }
        return;
    }

    // ---------------- einsum block: xw[cg-plane][k,tin,po][4co] -------------
    __shared__ float sw[4 * CIN * KSIZE];   // 192 weights of this co-group
    if (t < 4 * CIN * KSIZE) sw[t] = weight[cg * 4 * CIN * KSIZE + t];
    __syncthreads();
    if (t >= NLON_IN) return;

    const float* xp = x + tin * NLON_IN + t;
    float xv[CIN];
    #pragma unroll
    for (int ci = 0; ci < CIN; ci++) xv[ci] = __ldg(xp + ci * X_CI_STRIDE);

    float acc[12];
    #pragma unroll
    for (int j = 0; j < 12; j++) acc[j] = 0.0f;

    #pragma unroll
    for (int ci = 0; ci < CIN; ci++) {
        float xvv = xv[ci];
        #pragma unroll
        for (int cc = 0; cc < 4; cc++) {
            #pragma unroll
            for (int k = 0; k < KSIZE; k++) {
                acc[cc * 3 + k] = fmaf(sw[(cc * CIN + ci) * KSIZE + k], xvv, acc[cc * 3 + k]);
            }
        }
    }
    #pragma unroll
    for (int k = 0; k < KSIZE; k++) {
        __half2 lo = __floats2half2_rn(acc[0 * 3 + k], acc[1 * 3 + k]);
        __half2 hi = __floats2half2_rn(acc[2 * 3 + k], acc[3 * 3 + k]);
        uint2 u;
        u.x = *reinterpret_cast<unsigned int*>(&lo);
        u.y = *reinterpret_cast<unsigned int*>(&hi);
        g_xwp[cg][(k * NLAT_IN + tin) * NLON_IN + t] = u;
    }
}

// ---------------------------------------------------------------------------
// K2: gather — one block per output latitude; thread t owns lons (2t, 2t+1)
// for ALL 16 output channels, accumulating binned nonzeros in registers.
__global__ __launch_bounds__(384) void gather_kernel(
    float* __restrict__ out, const float* __restrict__ bias)
{
    const int ho = blockIdx.x;
    const int t  = threadIdx.x;
    const int nt = blockDim.x;

    __shared__ int2 se[SE_MAX];
    __shared__ int shdr[3];
    if (t < 3) shdr[t] = g_starts[2 * ho + t];
    __syncthreads();
    const int s0 = shdr[0], s1 = shdr[1], s2 = shdr[2];
    const int n = s2 - s0;

    const int2* ep;
    if (n <= SE_MAX) {
        for (int i = t; i < n; i += nt) se[i] = g_entries[s0 + i];
        __syncthreads();
        ep = se;
    } else {
        ep = &g_entries[s0];
    }

    if (t >= NLON_IN) return;

    float accE[16], accO[16];
    #pragma unroll
    for (int c = 0; c < 16; c++) { accE[c] = 0.0f; accO[c] = 0.0f; }

    const int nE = s1 - s0;
    // even parity -> wo = 2t
    for (int i = 0; i < nE; i++) {
        int2 e = ep[i];
        int shift = ((unsigned)e.x) >> 18;
        int base  = e.x & 0x3FFFF;
        float v   = __int_as_float(e.y);
        int idx = t - shift; if (idx < 0) idx += NLON_IN;
        int a = base + idx;
        #pragma unroll
        for (int cg = 0; cg < 4; cg++) {
            uint2 u = g_xwp[cg][a];
            float2 f0 = __half22float2(*reinterpret_cast<__half2*>(&u.x));
            float2 f1 = __half22float2(*reinterpret_cast<__half2*>(&u.y));
            accE[cg * 4 + 0] = fmaf(v, f0.x, accE[cg * 4 + 0]);
            accE[cg * 4 + 1] = fmaf(v, f0.y, accE[cg * 4 + 1]);
            accE[cg * 4 + 2] = fmaf(v, f1.x, accE[cg * 4 + 2]);
            accE[cg * 4 + 3] = fmaf(v, f1.y, accE[cg * 4 + 3]);
        }
    }
    // odd parity -> wo = 2t+1
    for (int i = nE; i < n; i++) {
        int2 e = ep[i];
        int shift = ((unsigned)e.x) >> 18;
        int base  = e.x & 0x3FFFF;
        float v   = __int_as_float(e.y);
        int idx = t - shift; if (idx < 0) idx += NLON_IN;
        int a = base + idx;
        #pragma unroll
        for (int cg = 0; cg < 4; cg++) {
            uint2 u = g_xwp[cg][a];
            float2 f0 = __half22float2(*reinterpret_cast<__half2*>(&u.x));
            float2 f1 = __half22float2(*reinterpret_cast<__half2*>(&u.y));
            accO[cg * 4 + 0] = fmaf(v, f0.x, accO[cg * 4 + 0]);
            accO[cg * 4 + 1] = fmaf(v, f0.y, accO[cg * 4 + 1]);
            accO[cg * 4 + 2] = fmaf(v, f1.x, accO[cg * 4 + 2]);
            accO[cg * 4 + 3] = fmaf(v, f1.y, accO[cg * 4 + 3]);
        }
    }

    #pragma unroll
    for (int co = 0; co < 16; co++) {
        float b = __ldg(&bias[co]);
        float2* row = (float2*)(out + (size_t)co * (NLAT_OUT * NLON_OUT) + ho * NLON_OUT);
        row[t] = make_float2(accE[co] + b, accO[co] + b);
    }
}

// ---------------------------------------------------------------------------
extern "C" void kernel_launch(void* const* d_in, const int* in_sizes, int n_in,
                              void* d_out, int out_size) {
    const float* x       = (const float*)d_in[0];
    const float* weight  = (const float*)d_in[1];
    const float* bias    = (const float*)d_in[2];
    const int*   ker_idx = (const int*)d_in[3];
    const int*   row_idx = (const int*)d_in[4];
    const int*   col_idx = (const int*)d_in[5];
    const float* vals    = (const float*)d_in[6];
    float* out = (float*)d_out;

    int nnz = in_sizes[3];
    if (nnz > NNZ_MAX) nnz = NNZ_MAX;

    dim3 egrid(NLAT_IN + 1, 4);
    einsum_prep_kernel<<<egrid, 384>>>(x, weight, ker_idx, row_idx, col_idx, vals, nnz);

    gather_kernel<<<NLAT_OUT, 384>>>(out, bias);
}

// round 3
// speedup vs baseline: 1.5854x; 1.5854x over previous
#include <cuda_runtime.h>
#include <cuda_fp16.h>
#include <stdint.h>

// Fixed problem shapes
#define NLAT_IN   181
#define NLON_IN   360
#define NLAT_OUT  361
#define NLON_OUT  720
#define KSIZE     3
#define CIN       16
#define COUT      16
#define NNZ_MAX   8192

#define X_CI_STRIDE (NLAT_IN * NLON_IN)          // 65160
#define PLANE       (KSIZE * NLAT_IN * NLON_IN)  // 195480
#define NBINS       (NLAT_OUT * 2)               // 722 (lat, parity)
#define SCAN_P      768
#define SE_MAX      512

// Scratch (device globals — no dynamic allocation allowed)
// Plane cg holds channels {8cg..8cg+7} as 8 packed halves (uint4) per (k,tin,po).
__device__ uint4 g_xw8[2][PLANE];        // 6.25 MB total, L2-resident
__device__ int   g_starts[NBINS + 2];
__device__ int2  g_entries[NNZ_MAX];     // .x = base(18b) | shift<<18 ; .y = bits(val)

// ---------------------------------------------------------------------------
// K1: channel-mix einsum (fp32 accum -> packed fp16 store) + fused binning.
// Flat grid of 2*NLAT_IN+1 blocks, 384 threads. Last block does the binning.
__global__ __launch_bounds__(384) void einsum_prep_kernel(
    const float* __restrict__ x, const float* __restrict__ weight,
    const int* __restrict__ ker_idx, const int* __restrict__ row_idx,
    const int* __restrict__ col_idx, const float* __restrict__ vals, int nnz)
{
    const int bx = blockIdx.x;
    const int t  = threadIdx.x;
    const int nt = blockDim.x;   // 384

    if (bx == 2 * NLAT_IN) {
        // ---------------- binning: count -> scan -> fill, all in smem --------
        __shared__ int bufA[SCAN_P], bufB[SCAN_P];
        __shared__ int scnt[NBINS], scur[NBINS];

        for (int i = t; i < SCAN_P; i += nt) bufA[i] = 0;
        __syncthreads();
        for (int i = t; i < nnz; i += nt) {
            int col = col_idx[i];
            int hi  = col / NLON_OUT;
            atomicAdd(&bufA[hi * 2 + (col & 1)], 1);   // p parity == col parity
        }
        __syncthreads();
        for (int i = t; i < NBINS; i += nt) scnt[i] = bufA[i];
        __syncthreads();
        // Hillis-Steele inclusive scan over SCAN_P, ping-pong buffers
        int* src = bufA; int* dst = bufB;
        for (int off = 1; off < SCAN_P; off <<= 1) {
            for (int i = t; i < SCAN_P; i += nt) {
                int v = src[i];
                if (i >= off) v += src[i - off];
                dst[i] = v;
            }
            __syncthreads();
            int* tmp = src; src = dst; dst = tmp;
        }
        for (int i = t; i < NBINS; i += nt) {
            g_starts[i + 1] = src[i];
            scur[i] = src[i] - scnt[i];    // exclusive prefix = bin start
        }
        if (t == 0) g_starts[0] = 0;
        __syncthreads();
        for (int i = t; i < nnz; i += nt) {
            int col = col_idx[i];
            int hi  = col / NLON_OUT;
            int p   = col - hi * NLON_OUT;
            int key = hi * 2 + (p & 1);
            int pos = atomicAdd(&scur[key], 1);
            int base = (ker_idx[i] * NLAT_IN + row_idx[i]) * NLON_IN;  // < 2^18
            g_entries[pos] = make_int2(base | ((p >> 1) << 18), __float_as_int(vals[i]));
        }
        return;
    }

    // ---------------- einsum block: 8 channels, one input latitude ----------
    const int tin = bx >> 1;
    const int cg  = bx & 1;        // channel group: channels cg*8 .. cg*8+7

    __shared__ float sw[8 * CIN * KSIZE];   // 384 weights of this co-group
    if (t < 8 * CIN * KSIZE) sw[t] = weight[cg * 8 * CIN * KSIZE + t];
    __syncthreads();
    if (t >= NLON_IN) return;

    const float* xp = x + tin * NLON_IN + t;
    float xv[CIN];
    #pragma unroll
    for (int ci = 0; ci < CIN; ci++) xv[ci] = __ldg(xp + ci * X_CI_STRIDE);

    float acc[24];   // [cc][k]
    #pragma unroll
    for (int j = 0; j < 24; j++) acc[j] = 0.0f;

    #pragma unroll
    for (int ci = 0; ci < CIN; ci++) {
        float xvv = xv[ci];
        #pragma unroll
        for (int cc = 0; cc < 8; cc++) {
            #pragma unroll
            for (int k = 0; k < KSIZE; k++) {
                acc[cc * 3 + k] = fmaf(sw[(cc * CIN + ci) * KSIZE + k], xvv, acc[cc * 3 + k]);
            }
        }
    }
    #pragma unroll
    for (int k = 0; k < KSIZE; k++) {
        __half2 h01 = __floats2half2_rn(acc[0 * 3 + k], acc[1 * 3 + k]);
        __half2 h23 = __floats2half2_rn(acc[2 * 3 + k], acc[3 * 3 + k]);
        __half2 h45 = __floats2half2_rn(acc[4 * 3 + k], acc[5 * 3 + k]);
        __half2 h67 = __floats2half2_rn(acc[6 * 3 + k], acc[7 * 3 + k]);
        uint4 u;
        u.x = *reinterpret_cast<unsigned int*>(&h01);
        u.y = *reinterpret_cast<unsigned int*>(&h23);
        u.z = *reinterpret_cast<unsigned int*>(&h45);
        u.w = *reinterpret_cast<unsigned int*>(&h67);
        g_xw8[cg][(k * NLAT_IN + tin) * NLON_IN + t] = u;
    }
}

// ---------------------------------------------------------------------------
// K2: gather — grid (NLAT_OUT, 2). Block (ho, cg): thread t owns output lons
// (2t, 2t+1) for channels {8cg..8cg+7}; one uint4 load per entry.
__global__ __launch_bounds__(384) void gather_kernel(
    float* __restrict__ out, const float* __restrict__ bias)
{
    const int ho = blockIdx.x;
    const int cg = blockIdx.y;
    const int t  = threadIdx.x;
    const int nt = blockDim.x;

    __shared__ int2 se[SE_MAX];
    __shared__ int shdr[3];
    if (t < 3) shdr[t] = g_starts[2 * ho + t];
    __syncthreads();
    const int s0 = shdr[0], s1 = shdr[1], s2 = shdr[2];
    const int n = s2 - s0;

    const int2* ep;
    if (n <= SE_MAX) {
        for (int i = t; i < n; i += nt) se[i] = g_entries[s0 + i];
        __syncthreads();
        ep = se;
    } else {
        ep = &g_entries[s0];
    }

    if (t >= NLON_IN) return;

    const uint4* __restrict__ plane = g_xw8[cg];

    float aE[8], aO[8];
    #pragma unroll
    for (int c = 0; c < 8; c++) { aE[c] = 0.0f; aO[c] = 0.0f; }

    const int nE = s1 - s0;
    // even parity -> wo = 2t
    #pragma unroll 2
    for (int i = 0; i < nE; i++) {
        int2 e = ep[i];
        int shift = ((unsigned)e.x) >> 18;
        int base  = e.x & 0x3FFFF;
        float v   = __int_as_float(e.y);
        int idx = t - shift; if (idx < 0) idx += NLON_IN;
        uint4 u = plane[base + idx];
        float2 f0 = __half22float2(*reinterpret_cast<__half2*>(&u.x));
        float2 f1 = __half22float2(*reinterpret_cast<__half2*>(&u.y));
        float2 f2 = __half22float2(*reinterpret_cast<__half2*>(&u.z));
        float2 f3 = __half22float2(*reinterpret_cast<__half2*>(&u.w));
        aE[0] = fmaf(v, f0.x, aE[0]);  aE[1] = fmaf(v, f0.y, aE[1]);
        aE[2] = fmaf(v, f1.x, aE[2]);  aE[3] = fmaf(v, f1.y, aE[3]);
        aE[4] = fmaf(v, f2.x, aE[4]);  aE[5] = fmaf(v, f2.y, aE[5]);
        aE[6] = fmaf(v, f3.x, aE[6]);  aE[7] = fmaf(v, f3.y, aE[7]);
    }
    // odd parity -> wo = 2t+1
    #pragma unroll 2
    for (int i = nE; i < n; i++) {
        int2 e = ep[i];
        int shift = ((unsigned)e.x) >> 18;
        int base  = e.x & 0x3FFFF;
        float v   = __int_as_float(e.y);
        int idx = t - shift; if (idx < 0) idx += NLON_IN;
        uint4 u = plane[base + idx];
        float2 f0 = __half22float2(*reinterpret_cast<__half2*>(&u.x));
        float2 f1 = __half22float2(*reinterpret_cast<__half2*>(&u.y));
        float2 f2 = __half22float2(*reinterpret_cast<__half2*>(&u.z));
        float2 f3 = __half22float2(*reinterpret_cast<__half2*>(&u.w));
        aO[0] = fmaf(v, f0.x, aO[0]);  aO[1] = fmaf(v, f0.y, aO[1]);
        aO[2] = fmaf(v, f1.x, aO[2]);  aO[3] = fmaf(v, f1.y, aO[3]);
        aO[4] = fmaf(v, f2.x, aO[4]);  aO[5] = fmaf(v, f2.y, aO[5]);
        aO[6] = fmaf(v, f3.x, aO[6]);  aO[7] = fmaf(v, f3.y, aO[7]);
    }

    #pragma unroll
    for (int c = 0; c < 8; c++) {
        int co = cg * 8 + c;
        float b = __ldg(&bias[co]);
        float2* row = (float2*)(out + (size_t)co * (NLAT_OUT * NLON_OUT) + ho * NLON_OUT);
        row[t] = make_float2(aE[c] + b, aO[c] + b);
    }
}

// ---------------------------------------------------------------------------
extern "C" void kernel_launch(void* const* d_in, const int* in_sizes, int n_in,
                              void* d_out, int out_size) {
    const float* x       = (const float*)d_in[0];
    const float* weight  = (const float*)d_in[1];
    const float* bias    = (const float*)d_in[2];
    const int*   ker_idx = (const int*)d_in[3];
    const int*   row_idx = (const int*)d_in[4];
    const int*   col_idx = (const int*)d_in[5];
    const float* vals    = (const float*)d_in[6];
    float* out = (float*)d_out;

    int nnz = in_sizes[3];
    if (nnz > NNZ_MAX) nnz = NNZ_MAX;

    einsum_prep_kernel<<<2 * NLAT_IN + 1, 384>>>(x, weight, ker_idx, row_idx,
                                                 col_idx, vals, nnz);
    dim3 ggrid(NLAT_OUT, 2);
    gather_kernel<<<ggrid, 384>>>(out, bias);
}